// round 8
// baseline (speedup 1.0000x reference)
#include <cuda_runtime.h>
#include <cuda_bf16.h>
#include <math.h>

#define N_NODES   100000
#define N_EDGES   1600000
#define NF        128
#define N_GRAPHS  1024

// ---------------- scratch (static device globals; no allocation) ----------------
__device__ float g_xw [N_NODES * NF];   // GEMM output (per-layer)
__device__ float g_h1 [N_NODES * NF];   // hidden ping
__device__ float g_h2 [N_NODES * NF];   // hidden pong
__device__ int   g_cnt   [N_NODES];
__device__ int   g_rowptr[N_NODES + 1];
__device__ int   g_cursor[N_NODES];
__device__ float g_isq   [N_NODES];     // deg^{-1/2}
__device__ float g_invdeg[N_NODES];     // 1/deg  (self-loop norm)
__device__ int   g_src   [N_EDGES];     // CSR (by dst) src node ids
__device__ float g_enorm [N_EDGES];     // per-edge norm
__device__ int   g_gstart[N_GRAPHS + 1];
__device__ int   g_is64;                // 1 if index inputs are int64, 0 if int32

// ---------------- dtype detection ----------------
// If edge_index is int64 (values < 1e5), the high 32-bit word of every element
// is 0. If it is int32, odd int32 slots hold random indices in [0, 1e5) and the
// probability all 128 sampled slots are 0 is ~0. One thread, trivial cost.
__global__ void detect_dtype_kernel(const int* __restrict__ ei32) {
    if (threadIdx.x != 0 || blockIdx.x != 0) return;
    int is64 = 1;
    #pragma unroll 1
    for (int i = 0; i < 128; i++) {
        if (ei32[2 * i + 1] != 0) { is64 = 0; break; }
    }
    g_is64 = is64;
}

__device__ __forceinline__ int load_idx(const void* p, long long i, bool is64) {
    return is64 ? (int)((const long long*)p)[i] : ((const int*)p)[i];
}

// ---------------- CSR build ----------------
__global__ void zero_cnt_kernel() {
    int i = blockIdx.x * blockDim.x + threadIdx.x;
    if (i < N_NODES) g_cnt[i] = 0;
}

__global__ void count_deg_kernel(const void* __restrict__ ei) {
    bool is64 = (g_is64 != 0);
    int stride = gridDim.x * blockDim.x;
    for (int e = blockIdx.x * blockDim.x + threadIdx.x; e < N_EDGES; e += stride) {
        int dst = load_idx(ei, (long long)N_EDGES + e, is64);
        if ((unsigned)dst < (unsigned)N_NODES)
            atomicAdd(&g_cnt[dst], 1);
    }
}

__global__ void compute_isq_kernel() {
    int i = blockIdx.x * blockDim.x + threadIdx.x;
    if (i >= N_NODES) return;
    float deg = (float)(g_cnt[i] + 1);      // +1 self loop; always >= 1
    g_isq[i]    = rsqrtf(deg);
    g_invdeg[i] = 1.0f / deg;
}

// single-block exclusive scan of g_cnt -> g_rowptr / g_cursor (4 elems/thread/chunk)
__global__ void scan_kernel() {
    __shared__ int wsum[32];
    __shared__ int carry_s;
    int tid = threadIdx.x, lane = tid & 31, wid = tid >> 5;
    if (tid == 0) carry_s = 0;
    __syncthreads();
    for (int base = 0; base < N_NODES; base += 4096) {
        int i0 = base + tid * 4;
        int v0 = 0, v1 = 0, v2 = 0, v3 = 0;
        if (i0 + 3 < N_NODES) {
            int4 t = *(const int4*)&g_cnt[i0];
            v0 = t.x; v1 = t.y; v2 = t.z; v3 = t.w;
        } else {
            if (i0     < N_NODES) v0 = g_cnt[i0];
            if (i0 + 1 < N_NODES) v1 = g_cnt[i0 + 1];
            if (i0 + 2 < N_NODES) v2 = g_cnt[i0 + 2];
            if (i0 + 3 < N_NODES) v3 = g_cnt[i0 + 3];
        }
        int ts = v0 + v1 + v2 + v3;
        int x = ts;
        #pragma unroll
        for (int o = 1; o < 32; o <<= 1) {
            int y = __shfl_up_sync(0xffffffffu, x, o);
            if (lane >= o) x += y;
        }
        if (lane == 31) wsum[wid] = x;
        __syncthreads();
        if (wid == 0) {
            int s = wsum[lane];
            #pragma unroll
            for (int o = 1; o < 32; o <<= 1) {
                int y = __shfl_up_sync(0xffffffffu, s, o);
                if (lane >= o) s += y;
            }
            wsum[lane] = s;
        }
        __syncthreads();
        int wexcl = wid ? wsum[wid - 1] : 0;
        int excl = x - ts + wexcl + carry_s;
        int e0 = excl, e1 = e0 + v0, e2 = e1 + v1, e3 = e2 + v2;
        if (i0     < N_NODES) { g_rowptr[i0]     = e0; g_cursor[i0]     = e0; }
        if (i0 + 1 < N_NODES) { g_rowptr[i0 + 1] = e1; g_cursor[i0 + 1] = e1; }
        if (i0 + 2 < N_NODES) { g_rowptr[i0 + 2] = e2; g_cursor[i0 + 2] = e2; }
        if (i0 + 3 < N_NODES) { g_rowptr[i0 + 3] = e3; g_cursor[i0 + 3] = e3; }
        __syncthreads();
        if (tid == 1023) carry_s += wsum[31];
        __syncthreads();
    }
    if (threadIdx.x == 0) g_rowptr[N_NODES] = carry_s;
}

__global__ void scatter_edges_kernel(const void* __restrict__ ei) {
    bool is64 = (g_is64 != 0);
    int stride = gridDim.x * blockDim.x;
    for (int e = blockIdx.x * blockDim.x + threadIdx.x; e < N_EDGES; e += stride) {
        int src = load_idx(ei, e, is64);
        int dst = load_idx(ei, (long long)N_EDGES + e, is64);
        if ((unsigned)src >= (unsigned)N_NODES) continue;
        if ((unsigned)dst >= (unsigned)N_NODES) continue;
        int pos = atomicAdd(&g_cursor[dst], 1);
        if ((unsigned)pos < (unsigned)N_EDGES) {
            g_src[pos]   = src;
            g_enorm[pos] = g_isq[src] * g_isq[dst];
        }
    }
}

// ---------------- GEMM: g_xw[M x 128] = A[M x 128] @ W[128 x 128] ----------------
// selA: 0 -> external x, 1 -> g_h1, 2 -> g_h2.  Output always g_xw.
// Static shared only: As 64x128 (32KB) + Ws chunk 32x128 (16KB) = 48KB.
__global__ __launch_bounds__(256) void gemm128_kernel(
    const float* __restrict__ xin, int selA, const float* __restrict__ W, int M)
{
    __shared__ float As[64 * 128];
    __shared__ float Ws[32 * 128];
    const float* A = (selA == 0) ? xin : (selA == 1 ? g_h1 : g_h2);
    int tid = threadIdx.x;
    int m0 = blockIdx.x * 64;

    // load A tile (64 rows x 128 cols), float4-wide
    #pragma unroll
    for (int i = 0; i < 8; i++) {
        int f4 = tid + i * 256;                 // 2048 float4 total
        int r = f4 >> 5;
        int c = (f4 & 31) * 4;
        int row = m0 + r;
        float4 v = make_float4(0.f, 0.f, 0.f, 0.f);
        if (row < M) v = *(const float4*)&A[row * NF + c];
        *(float4*)&As[r * NF + c] = v;
    }

    int tn = (tid & 31) * 4;
    int tm = (tid >> 5) * 8;
    float acc[8][4];
    #pragma unroll
    for (int j = 0; j < 8; j++)
        #pragma unroll
        for (int n = 0; n < 4; n++) acc[j][n] = 0.f;

    #pragma unroll
    for (int kc = 0; kc < 4; kc++) {            // four 32-row chunks of W
        __syncthreads();
        #pragma unroll
        for (int i = 0; i < 4; i++) {
            int idx = (tid + i * 256) * 4;      // 1024 float4 = 32*128 floats
            *(float4*)&Ws[idx] = *(const float4*)&W[kc * 32 * NF + idx];
        }
        __syncthreads();
        #pragma unroll 8
        for (int kk = 0; kk < 32; kk++) {
            int k = kc * 32 + kk;
            float4 w = *(float4*)&Ws[kk * NF + tn];
            #pragma unroll
            for (int j = 0; j < 8; j++) {
                float a = As[(tm + j) * NF + k];
                acc[j][0] += a * w.x;
                acc[j][1] += a * w.y;
                acc[j][2] += a * w.z;
                acc[j][3] += a * w.w;
            }
        }
    }
    #pragma unroll
    for (int j = 0; j < 8; j++) {
        int row = m0 + tm + j;
        if (row < M)
            *(float4*)&g_xw[row * NF + tn] =
                make_float4(acc[j][0], acc[j][1], acc[j][2], acc[j][3]);
    }
}

// ---------------- aggregation: warp per node, CSR gather, +self, +bias, relu ----
// selOut: 1 -> g_h1, 2 -> g_h2
__global__ __launch_bounds__(256) void aggregate_kernel(
    const float* __restrict__ bias, int selOut)
{
    int node = (blockIdx.x * blockDim.x + threadIdx.x) >> 5;
    if (node >= N_NODES) return;
    float* out = (selOut == 1) ? g_h1 : g_h2;
    int lane = threadIdx.x & 31;
    int beg = g_rowptr[node];
    int end = g_rowptr[node + 1];
    float ax = 0.f, ay = 0.f, az = 0.f, aw = 0.f;
    int col = lane * 4;
    for (int e = beg; e < end; e++) {
        int   s = g_src[e];
        float w = g_enorm[e];
        float4 v = *(const float4*)&g_xw[s * NF + col];
        ax += w * v.x; ay += w * v.y; az += w * v.z; aw += w * v.w;
    }
    // self loop
    float sd = g_invdeg[node];
    float4 vs = *(const float4*)&g_xw[node * NF + col];
    ax += sd * vs.x; ay += sd * vs.y; az += sd * vs.z; aw += sd * vs.w;
    // bias + relu
    float4 b = *(const float4*)&bias[col];
    ax = fmaxf(ax + b.x, 0.f);
    ay = fmaxf(ay + b.y, 0.f);
    az = fmaxf(az + b.z, 0.f);
    aw = fmaxf(aw + b.w, 0.f);
    *(float4*)&out[node * NF + col] = make_float4(ax, ay, az, aw);
}

// ---------------- pooling + FC ----------------
__global__ void graph_bounds_kernel(const void* __restrict__ batch) {
    bool is64 = (g_is64 != 0);
    int g = blockIdx.x * blockDim.x + threadIdx.x;
    if (g > N_GRAPHS) return;
    int lo = 0, hi = N_NODES;
    while (lo < hi) {
        int mid = (lo + hi) >> 1;
        int bv = load_idx(batch, mid, is64);
        if (bv < g) lo = mid + 1; else hi = mid;
    }
    g_gstart[g] = lo;
}

__global__ void pool_fc_kernel(const float* __restrict__ Wfc,
                               const float* __restrict__ bfc,
                               float* __restrict__ out)
{
    __shared__ float red[128];
    int g = blockIdx.x;
    int t = threadIdx.x;            // 128
    int beg = g_gstart[g], end = g_gstart[g + 1];
    if (beg < 0) beg = 0;
    if (end > N_NODES) end = N_NODES;
    float s = 0.f;
    for (int n = beg; n < end; n++) s += g_h1[n * NF + t];
    float cnt = (float)(end - beg);
    float mean = (cnt > 0.f) ? (s / cnt) : 0.f;
    red[t] = mean * Wfc[t];
    __syncthreads();
    #pragma unroll
    for (int o = 64; o > 0; o >>= 1) {
        if (t < o) red[t] += red[t + o];
        __syncthreads();
    }
    if (t == 0) out[g] = red[0] + bfc[0];
}

// ---------------- launch ----------------
extern "C" void kernel_launch(void* const* d_in, const int* in_sizes, int n_in,
                              void* d_out, int out_size) {
    const float* x     = (const float*)d_in[0];
    const void*  ei    = d_in[1];
    const void*  batch = d_in[2];
    const float* W1  = (const float*)d_in[3];
    const float* b1  = (const float*)d_in[4];
    const float* W2  = (const float*)d_in[5];
    const float* b2  = (const float*)d_in[6];
    const float* W3  = (const float*)d_in[7];
    const float* b3  = (const float*)d_in[8];
    const float* Wfc = (const float*)d_in[9];
    const float* bfc = (const float*)d_in[10];
    float* out = (float*)d_out;

    // dtype probe (int64 vs int32 index buffers), then CSR build
    detect_dtype_kernel<<<1, 32>>>((const int*)ei);
    zero_cnt_kernel<<<(N_NODES + 255) / 256, 256>>>();
    count_deg_kernel<<<2048, 256>>>(ei);
    compute_isq_kernel<<<(N_NODES + 255) / 256, 256>>>();
    scan_kernel<<<1, 1024>>>();
    scatter_edges_kernel<<<2048, 256>>>(ei);

    const int GEMM_BLOCKS = (N_NODES + 63) / 64;
    const int AGG_BLOCKS  = (N_NODES * 32 + 255) / 256;

    // layer 1
    gemm128_kernel<<<GEMM_BLOCKS, 256>>>(x, 0, W1, N_NODES);
    aggregate_kernel<<<AGG_BLOCKS, 256>>>(b1, 1);
    // layer 2
    gemm128_kernel<<<GEMM_BLOCKS, 256>>>(x, 1, W2, N_NODES);
    aggregate_kernel<<<AGG_BLOCKS, 256>>>(b2, 2);
    // layer 3
    gemm128_kernel<<<GEMM_BLOCKS, 256>>>(x, 2, W3, N_NODES);
    aggregate_kernel<<<AGG_BLOCKS, 256>>>(b3, 1);

    // pool + fc
    graph_bounds_kernel<<<(N_GRAPHS + 1 + 255) / 256, 256>>>(batch);
    pool_fc_kernel<<<N_GRAPHS, 128>>>(Wfc, bfc, out);
}